// round 6
// baseline (speedup 1.0000x reference)
#include <cuda_runtime.h>
#include <cuda_bf16.h>
#include <cstdint>

#define NPTS 65536
#define MPTS 65536
#define KNB  16
#define NTILES 4096          // MPTS*KNB / 256
#define GRID 148

// ---------------- device scratch ----------------
__device__ __align__(16) unsigned short g_xhi[(size_t)NPTS * 64];
__device__ __align__(16) unsigned short g_xlo[(size_t)NPTS * 64];
__device__ __align__(16) unsigned short g_w1hi[64 * 64];
__device__ __align__(16) unsigned short g_w1lo[64 * 64];
__device__ __align__(16) unsigned short g_w2hi[128 * 64];
__device__ __align__(16) unsigned short g_w2lo[128 * 64];
__device__ float g_w1pos[64 * 4];
__device__ int   g_idx_is64;

// ---------------- smem layout (bytes) ----------------
#define SM_W1HI 0                       // 64*144
#define SM_W1LO 9216
#define SM_W2HI 18432                   // 128*144
#define SM_W2LO 36864
#define SM_BUF0 55296                   // 256*144 hi + 256*144 lo = 73728
#define SM_BUF1 129024
#define SM_PD0  202752                  // 3*256*4
#define SM_PD1  205824
#define SM_W1P  208896                  // 64*16
#define SM_POOL 209920                  // 128*20*4
#define SM_TOTAL 220160

#define BUF_LO_OFF 36864                // lo plane offset within a buffer

// ---------------- helpers ----------------
__device__ __forceinline__ uint32_t smem_u32(const void* p) {
    uint32_t a;
    asm("{ .reg .u64 t; cvta.to.shared.u64 t, %1; cvt.u32.u64 %0, t; }" : "=r"(a) : "l"(p));
    return a;
}
__device__ __forceinline__ void ldsm4(uint32_t (&r)[4], uint32_t addr) {
    asm volatile("ldmatrix.sync.aligned.m8n8.x4.shared.b16 {%0,%1,%2,%3}, [%4];"
                 : "=r"(r[0]), "=r"(r[1]), "=r"(r[2]), "=r"(r[3]) : "r"(addr));
}
__device__ __forceinline__ void mma16816(float (&d)[4], const uint32_t (&a)[4],
                                         uint32_t b0, uint32_t b1) {
    asm volatile("mma.sync.aligned.m16n8k16.row.col.f32.bf16.bf16.f32 "
                 "{%0,%1,%2,%3}, {%4,%5,%6,%7}, {%8,%9}, {%0,%1,%2,%3};"
                 : "+f"(d[0]), "+f"(d[1]), "+f"(d[2]), "+f"(d[3])
                 : "r"(a[0]), "r"(a[1]), "r"(a[2]), "r"(a[3]), "r"(b0), "r"(b1));
}
#define CP16(dst, src) \
    asm volatile("cp.async.cg.shared.global [%0], [%1], 16;" :: "r"(dst), "l"(src))
#define CP_COMMIT()  asm volatile("cp.async.commit_group;" ::: "memory")
#define CP_WAIT0()   asm volatile("cp.async.wait_group 0;" ::: "memory")

// ---------------- prep: x -> bf16 hi/lo rows ----------------
__global__ __launch_bounds__(256) void prep_x_kernel(const float* __restrict__ x)
{
    __shared__ unsigned short shhi[128 * 72];
    __shared__ unsigned short shlo[128 * 72];
    const int p0 = blockIdx.x * 128;
    const int tid = threadIdx.x;

    for (int idx = tid; idx < 128 * 64; idx += 256) {
        int c = idx >> 7, p = idx & 127;
        float v = x[(size_t)c * NPTS + p0 + p];
        __nv_bfloat16 h = __float2bfloat16(v);
        __nv_bfloat16 l = __float2bfloat16(v - __bfloat162float(h));
        shhi[p * 72 + c] = *(unsigned short*)&h;
        shlo[p * 72 + c] = *(unsigned short*)&l;
    }
    __syncthreads();
    uint4* dh = (uint4*)(g_xhi + (size_t)p0 * 64);
    uint4* dl = (uint4*)(g_xlo + (size_t)p0 * 64);
    for (int i = tid; i < 1024; i += 256) {
        int p = i >> 3, q = i & 7;
        dh[i] = *(const uint4*)&shhi[p * 72 + q * 8];
        dl[i] = *(const uint4*)&shlo[p * 72 + q * 8];
    }
}

// ---------------- prep: weights ----------------
__global__ __launch_bounds__(256) void prep_w_kernel(const float* __restrict__ W1,
                                                     const float* __restrict__ W2,
                                                     const unsigned int* __restrict__ idx32)
{
    int tid = blockIdx.x * blockDim.x + threadIdx.x;
    if (tid == 0) {
        unsigned int orv = 0;
        for (int i = 0; i < 256; i++) orv |= idx32[2 * i + 1];
        g_idx_is64 = (orv == 0u) ? 1 : 0;
    }
    if (tid < 64 * 64) {
        int o = tid >> 6, k = tid & 63;
        float v = W1[o * 67 + k];
        __nv_bfloat16 h = __float2bfloat16(v);
        __nv_bfloat16 l = __float2bfloat16(v - __bfloat162float(h));
        g_w1hi[tid] = *(unsigned short*)&h;
        g_w1lo[tid] = *(unsigned short*)&l;
    }
    if (tid < 64) {
        g_w1pos[tid * 4 + 0] = W1[tid * 67 + 64];
        g_w1pos[tid * 4 + 1] = W1[tid * 67 + 65];
        g_w1pos[tid * 4 + 2] = W1[tid * 67 + 66];
        g_w1pos[tid * 4 + 3] = 0.0f;
    }
    if (tid < 128 * 64) {
        float v = W2[tid];
        __nv_bfloat16 h = __float2bfloat16(v);
        __nv_bfloat16 l = __float2bfloat16(v - __bfloat162float(h));
        g_w2hi[tid] = *(unsigned short*)&h;
        g_w2lo[tid] = *(unsigned short*)&l;
    }
}

// ---------------- main persistent kernel ----------------
extern __shared__ char smc[];

__global__ __launch_bounds__(512, 1)
void pointnet_mma_kernel(const float* __restrict__ pos,
                         const float* __restrict__ sup,
                         const float* __restrict__ b1,
                         const float* __restrict__ b2,
                         const void* __restrict__ indices,
                         float* __restrict__ out)
{
    const uint32_t sb = smem_u32(smc);
    const int tid = threadIdx.x;
    const int w = tid >> 5;
    const int l = tid & 31;
    const int is64 = g_idx_is64;

    // ---- stage weights once ----
    for (int i = tid; i < 1024; i += 512) {          // W1 hi/lo
        int buf = i >> 9, o = (i >> 3) & 63, c = i & 7;
        const uint4* s = (const uint4*)((buf ? g_w1lo : g_w1hi) + o * 64);
        *(uint4*)(smc + SM_W1HI + buf * 9216 + o * 144 + c * 16) = s[c];
    }
    for (int i = tid; i < 2048; i += 512) {          // W2 hi/lo
        int buf = i >> 10, o = (i >> 3) & 127, c = i & 7;
        const uint4* s = (const uint4*)((buf ? g_w2lo : g_w2hi) + o * 64);
        *(uint4*)(smc + SM_W2HI + buf * 18432 + o * 144 + c * 16) = s[c];
    }
    if (tid < 256) *(float*)(smc + SM_W1P + tid * 4) = g_w1pos[tid];

    float* poolf = (float*)(smc + SM_POOL);

    // gather thread mapping: row p = tid>>1, plane = tid&1 (hi/lo), 8 chunks
    const int gp    = tid >> 1;
    const int plane = tid & 1;

    auto load_idx = [&](long long lin) -> int {
        if (is64) return (int)((const long long*)indices)[lin] & (NPTS - 1);
        return ((const int*)indices)[lin] & (NPTS - 1);
    };

    // issue cp.async gather of one tile into buffer at byte offset bufB
    auto issue_gather = [&](int ii, uint32_t bufB) {
        const char* src = (const char*)((plane ? g_xlo : g_xhi) + (size_t)ii * 64);
        uint32_t dst = sb + bufB + (uint32_t)plane * BUF_LO_OFF + (uint32_t)gp * 144;
#pragma unroll
        for (int c = 0; c < 8; c++)
            CP16(dst + c * 16, src + c * 16);
        CP_COMMIT();
    };

    // ---- prologue: gather tile0 ----
    int tile = blockIdx.x;
    {
        int ii = load_idx((long long)tile * 256 + gp);
        issue_gather(ii, SM_BUF0);
        if (tid < 256) {
            int iipd = load_idx((long long)tile * 256 + tid);
            int m = tile * 16 + (tid >> 4);
            float* pdf = (float*)(smc + SM_PD0);
#pragma unroll
            for (int d = 0; d < 3; d++)
                pdf[d * 256 + tid] = pos[d * NPTS + iipd] - sup[d * MPTS + m];
        }
        CP_WAIT0();
    }
    __syncthreads();

    int bufsel = 0;
    for (; tile < NTILES; tile += GRID) {
        const uint32_t curB = bufsel ? SM_BUF1 : SM_BUF0;
        const uint32_t nxtB = bufsel ? SM_BUF0 : SM_BUF1;
        float* pdf_cur = (float*)(smc + (bufsel ? SM_PD1 : SM_PD0));
        float* pdf_nxt = (float*)(smc + (bufsel ? SM_PD0 : SM_PD1));

        int pf_tile = tile + GRID;
        if (pf_tile >= NTILES) pf_tile = tile;      // safe redundant prefetch

        // prefetch indices for next tile (latency hidden by GEMM1)
        int ii_nx   = load_idx((long long)pf_tile * 256 + gp);
        int ii_pdnx = 0;
        if (tid < 256) ii_pdnx = load_idx((long long)pf_tile * 256 + tid);

        // ================= GEMM1: 64 x 256, K=64 =================
        const int wm1 = w & 3, wn1 = w >> 2;
        {
            const int o0 = wm1 * 16;
            float acc[8][4];
#pragma unroll
            for (int i = 0; i < 8; i++)
#pragma unroll
                for (int j = 0; j < 4; j++) acc[i][j] = 0.0f;

            const uint32_t arowH = sb + SM_W1HI +
                (o0 + ((l >> 3) & 1) * 8 + (l & 7)) * 144;
            const uint32_t arowL = arowH + 9216;
            const uint32_t browH = sb + curB +
                (wn1 * 64 + ((l >> 4) & 1) * 8 + (l & 7)) * 144;
            const uint32_t browL = browH + BUF_LO_OFF;

#pragma unroll
            for (int ks = 0; ks < 4; ks++) {
                uint32_t ach = (2 * ks + (l >> 4)) * 16;
                uint32_t bch = (2 * ks + ((l >> 3) & 1)) * 16;
                uint32_t ah[4], al[4];
                ldsm4(ah, arowH + ach);
                ldsm4(al, arowL + ach);
#pragma unroll
                for (int nbp = 0; nbp < 4; nbp++) {
                    uint32_t bh[4], bl[4];
                    ldsm4(bh, browH + nbp * (16 * 144) + bch);
                    mma16816(acc[2 * nbp],     ah, bh[0], bh[1]);
                    mma16816(acc[2 * nbp + 1], ah, bh[2], bh[3]);
                    mma16816(acc[2 * nbp],     al, bh[0], bh[1]);
                    mma16816(acc[2 * nbp + 1], al, bh[2], bh[3]);
                    ldsm4(bl, browL + nbp * (16 * 144) + bch);
                    mma16816(acc[2 * nbp],     ah, bl[0], bl[1]);
                    mma16816(acc[2 * nbp + 1], ah, bl[2], bl[3]);
                }
            }

            // ---- launch async gather for next tile (hides under epi+GEMM2) ----
            issue_gather(ii_nx, nxtB);
            float pdv[3];
            if (tid < 256) {
                int m = pf_tile * 16 + (tid >> 4);
#pragma unroll
                for (int d = 0; d < 3; d++)
                    pdv[d] = pos[d * NPTS + ii_pdnx] - sup[d * MPTS + m];
            }

            // all 4 warps of this wn-group done reading B rows -> safe to overwrite with H
            asm volatile("bar.sync %0, %1;" :: "r"(wn1 + 1), "r"(128) : "memory");

            // ---- epilogue 1: pos-term + bias + relu -> H (hi/lo) into curB ----
            const int o_lo = o0 + (l >> 2);
            const int o_hi = o_lo + 8;
            float4 wpl = *(const float4*)(smc + SM_W1P + o_lo * 16);
            float4 wph = *(const float4*)(smc + SM_W1P + o_hi * 16);
            float bl_ = __ldg(&b1[o_lo]);
            float bh_ = __ldg(&b1[o_hi]);
            const int paired = (((l >> 2) & 1) == 0);

#pragma unroll
            for (int nb = 0; nb < 8; nb++) {
                int cb = wn1 * 64 + nb * 8 + (l & 3) * 2;
                float2 q0 = *(const float2*)&pdf_cur[0 * 256 + cb];
                float2 q1 = *(const float2*)&pdf_cur[1 * 256 + cb];
                float2 q2 = *(const float2*)&pdf_cur[2 * 256 + cb];
                float v[4];
                v[0] = fmaxf(acc[nb][0] + bl_ + wpl.x * q0.x + wpl.y * q1.x + wpl.z * q2.x, 0.0f);
                v[1] = fmaxf(acc[nb][1] + bl_ + wpl.x * q0.y + wpl.y * q1.y + wpl.z * q2.y, 0.0f);
                v[2] = fmaxf(acc[nb][2] + bh_ + wph.x * q0.x + wph.y * q1.x + wph.z * q2.x, 0.0f);
                v[3] = fmaxf(acc[nb][3] + bh_ + wph.x * q0.y + wph.y * q1.y + wph.z * q2.y, 0.0f);
                const int colv[4] = {cb, cb + 1, cb, cb + 1};
                const int ov[4]   = {o_lo, o_lo, o_hi, o_hi};
#pragma unroll
                for (int q = 0; q < 4; q++) {
                    __nv_bfloat16 hb = __float2bfloat16(v[q]);
                    float rem = v[q] - __bfloat162float(hb);
                    __nv_bfloat16 lb = __float2bfloat16(rem);
                    uint32_t uh = (uint32_t)(*(unsigned short*)&hb);
                    uint32_t ul = (uint32_t)(*(unsigned short*)&lb);
                    uint32_t ph = __shfl_xor_sync(0xffffffffu, uh, 4);
                    uint32_t pl = __shfl_xor_sync(0xffffffffu, ul, 4);
                    if (paired) {
                        uint32_t off = colv[q] * 144 + ov[q] * 2;
                        *(uint32_t*)(smc + curB + off) = uh | (ph << 16);
                        *(uint32_t*)(smc + curB + BUF_LO_OFF + off) = ul | (pl << 16);
                    }
                }
            }

            // store next tile's pos diffs (LDGs have landed during epilogue)
            if (tid < 256) {
#pragma unroll
                for (int d = 0; d < 3; d++)
                    pdf_nxt[d * 256 + tid] = pdv[d];
            }
        }
        __syncthreads();

        // ================= GEMM2: 128 x 256, K=64 + max-pool =================
        {
            const int wm = w & 7, wn = w >> 3;
            const int o0 = wm * 16;
            float acc[16][4];
#pragma unroll
            for (int i = 0; i < 16; i++)
#pragma unroll
                for (int j = 0; j < 4; j++) acc[i][j] = 0.0f;

            const uint32_t arowH = sb + SM_W2HI +
                (o0 + ((l >> 3) & 1) * 8 + (l & 7)) * 144;
            const uint32_t arowL = arowH + 18432;
            const uint32_t browH = sb + curB +
                (wn * 128 + ((l >> 4) & 1) * 8 + (l & 7)) * 144;
            const uint32_t browL = browH + BUF_LO_OFF;

#pragma unroll
            for (int ks = 0; ks < 4; ks++) {
                uint32_t ach = (2 * ks + (l >> 4)) * 16;
                uint32_t bch = (2 * ks + ((l >> 3) & 1)) * 16;
                uint32_t ah[4], al[4];
                ldsm4(ah, arowH + ach);
                ldsm4(al, arowL + ach);
#pragma unroll
                for (int nbp = 0; nbp < 8; nbp++) {
                    uint32_t bh[4], bl[4];
                    ldsm4(bh, browH + nbp * (16 * 144) + bch);
                    mma16816(acc[2 * nbp],     ah, bh[0], bh[1]);
                    mma16816(acc[2 * nbp + 1], ah, bh[2], bh[3]);
                    mma16816(acc[2 * nbp],     al, bh[0], bh[1]);
                    mma16816(acc[2 * nbp + 1], al, bh[2], bh[3]);
                    ldsm4(bl, browL + nbp * (16 * 144) + bch);
                    mma16816(acc[2 * nbp],     ah, bl[0], bl[1]);
                    mma16816(acc[2 * nbp + 1], ah, bl[2], bl[3]);
                }
            }

            // ---- pool over K=16 ----
#pragma unroll
            for (int nbp = 0; nbp < 8; nbp++) {
                float mlo = fmaxf(fmaxf(acc[2 * nbp][0], acc[2 * nbp][1]),
                                  fmaxf(acc[2 * nbp + 1][0], acc[2 * nbp + 1][1]));
                float mhi = fmaxf(fmaxf(acc[2 * nbp][2], acc[2 * nbp][3]),
                                  fmaxf(acc[2 * nbp + 1][2], acc[2 * nbp + 1][3]));
                mlo = fmaxf(mlo, __shfl_xor_sync(0xffffffffu, mlo, 1));
                mlo = fmaxf(mlo, __shfl_xor_sync(0xffffffffu, mlo, 2));
                mhi = fmaxf(mhi, __shfl_xor_sync(0xffffffffu, mhi, 1));
                mhi = fmaxf(mhi, __shfl_xor_sync(0xffffffffu, mhi, 2));
                if ((l & 3) == 0) {
                    int mp = wn * 8 + nbp;
                    poolf[(o0 + (l >> 2)) * 20 + mp]     = mlo;
                    poolf[(o0 + 8 + (l >> 2)) * 20 + mp] = mhi;
                }
            }
        }
        __syncthreads();

        // ---- coalesced output ----
        {
            int o = tid >> 2, mg = tid & 3;
            float4 v = *(const float4*)(poolf + o * 20 + mg * 4);
            float bb = __ldg(&b2[o]);
            v.x += bb; v.y += bb; v.z += bb; v.w += bb;
            *(float4*)(out + (size_t)o * MPTS + tile * 16 + mg * 4) = v;
        }

        CP_WAIT0();          // next tile's gather data ready
        __syncthreads();
        bufsel ^= 1;
    }
}

// ---------------------------------------------------------------------------
extern "C" void kernel_launch(void* const* d_in, const int* in_sizes, int n_in,
                              void* d_out, int out_size)
{
    const float *x = 0, *pos = 0, *sup = 0, *W1 = 0, *b1 = 0, *W2 = 0, *b2 = 0;
    const void* idx = 0;
    for (int i = 0; i < n_in; i++) {
        switch (in_sizes[i]) {
            case 4194304: x  = (const float*)d_in[i]; break;
            case 196608:  if (!pos) pos = (const float*)d_in[i];
                          else      sup = (const float*)d_in[i]; break;
            case 4288:    W1 = (const float*)d_in[i]; break;
            case 64:      b1 = (const float*)d_in[i]; break;
            case 8192:    W2 = (const float*)d_in[i]; break;
            case 128:     b2 = (const float*)d_in[i]; break;
            case 1048576: idx = d_in[i]; break;
            default: break;
        }
    }
    float* out = (float*)d_out;

    prep_w_kernel<<<32, 256>>>(W1, W2, (const unsigned int*)idx);
    prep_x_kernel<<<NPTS / 128, 256>>>(x);

    cudaFuncSetAttribute(pointnet_mma_kernel,
                         cudaFuncAttributeMaxDynamicSharedMemorySize, SM_TOTAL);
    pointnet_mma_kernel<<<GRID, 512, SM_TOTAL>>>(pos, sup, b1, b2, idx, out);
}